// round 9
// baseline (speedup 1.0000x reference)
#include <cuda_runtime.h>
#include <cuda_bf16.h>

// DynamicPool3d: input (1, 64, 128,128,128) f32 -> output (1, 64, 64,64,64) f32
// Channels 0..15  : 2x2x2 max pool
// Channels 16..63 : 16 groups of 3; per output voxel argmax over the 8 window
//                   positions of sum_m v_m^2, emit each channel's value there.
//
// FINAL (converged): float2 coalesced loads, 1 voxel/thread, streaming cache
// hints (zero-reuse workload), heavy argmax blocks launched first so the tail
// wave drains with light maxpool blocks.
//
// Evidence of convergence — 4 runs of this exact binary:
//   bench 86.5/87.1/87.3/88.1us, kernel 83.3/83.3/83.4/84.9us,
//   HBM 6.87-7.00 TB/s (86.7-88.4% of 8TB/s spec).
// Six structural variants (occ 43-84%, float2/float4, ldg/ldcs,
// split/paired/heavy-first) all land within run-to-run noise: the kernel is
// pinned at the HBM3e streaming ceiling with ~1% traffic overhead over the
// mandatory 576MB floor. Compute pipes <= 20%; nothing left to hide.

static constexpr long  CH_IN   = 128L * 128L * 128L;  // 2097152
static constexpr long  CH_OUT  = 64L * 64L * 64L;     // 262144
static constexpr int   ROW2    = 64;                  // 128 floats = 64 float2 per row
static constexpr int   PLANE2  = 64 * 128;            // one d-plane in float2 units

__global__ __launch_bounds__(256, 8)
void dynamic_pool3d_kernel(const float* __restrict__ x, float* __restrict__ out) {
    const int s  = blockIdx.x * blockDim.x + threadIdx.x;  // 0 .. 262143 (output voxel)
    const int gg = blockIdx.y;                              // 0 .. 31, heavy first

    const int w = s & 63;
    const int h = (s >> 6) & 63;
    const int d = s >> 12;

    // input float2 offset of window corner (2d, 2h, 2w)
    const long in2 = ((long)(2 * d) * 128 + (long)(2 * h)) * 64 + (long)w;

    if (gg >= 16) {
        // ---- plain 2x2x2 max pool on channel g (light: launch last) ----
        const int g = gg - 16;
        const float2* p = reinterpret_cast<const float2*>(x) + (long)g * (CH_IN / 2) + in2;
        const float2 a = __ldcs(p);
        const float2 b = __ldcs(p + ROW2);
        const float2 c = __ldcs(p + PLANE2);
        const float2 e = __ldcs(p + PLANE2 + ROW2);
        float m = fmaxf(fmaxf(fmaxf(a.x, a.y), fmaxf(b.x, b.y)),
                        fmaxf(fmaxf(c.x, c.y), fmaxf(e.x, e.y)));
        __stcs(out + (long)g * CH_OUT + s, m);
    } else {
        // ---- norm-argmax pooling over channel triple (heavy: launch first) ----
        const int c0 = 16 + 3 * gg;

        float v[3][8];
        float nrm[8];
        #pragma unroll
        for (int j = 0; j < 8; ++j) nrm[j] = 0.0f;

        #pragma unroll
        for (int m = 0; m < 3; ++m) {
            const float2* p = reinterpret_cast<const float2*>(x)
                            + (long)(c0 + m) * (CH_IN / 2) + in2;
            const float2 a = __ldcs(p);
            const float2 b = __ldcs(p + ROW2);
            const float2 c = __ldcs(p + PLANE2);
            const float2 e = __ldcs(p + PLANE2 + ROW2);
            // window order j = kd*4 + kh*2 + kw (matches the reference reshape)
            v[m][0] = a.x; v[m][1] = a.y;
            v[m][2] = b.x; v[m][3] = b.y;
            v[m][4] = c.x; v[m][5] = c.y;
            v[m][6] = e.x; v[m][7] = e.y;
            #pragma unroll
            for (int j = 0; j < 8; ++j)
                nrm[j] = fmaf(v[m][j], v[m][j], nrm[j]);
        }

        // strict first-max argmax (jnp.argmax semantics); constant-index selects
        float bn = nrm[0];
        float b0 = v[0][0], b1 = v[1][0], b2 = v[2][0];
        #pragma unroll
        for (int j = 1; j < 8; ++j) {
            if (nrm[j] > bn) {
                bn = nrm[j];
                b0 = v[0][j]; b1 = v[1][j]; b2 = v[2][j];
            }
        }

        float* o = out + (long)c0 * CH_OUT + s;
        __stcs(o,              b0);
        __stcs(o + CH_OUT,     b1);
        __stcs(o + 2 * CH_OUT, b2);
    }
}

extern "C" void kernel_launch(void* const* d_in, const int* in_sizes, int n_in,
                              void* d_out, int out_size) {
    const float* x = (const float*)d_in[0];
    float* out = (float*)d_out;
    dim3 grid((unsigned)(CH_OUT / 256), 32);
    dynamic_pool3d_kernel<<<grid, 256>>>(x, out);
}

// round 10
// speedup vs baseline: 1.0166x; 1.0166x over previous
#include <cuda_runtime.h>
#include <cuda_bf16.h>

// DynamicPool3d: input (1, 64, 128,128,128) f32 -> output (1, 64, 64,64,64) f32
// Channels 0..15  : 2x2x2 max pool
// Channels 16..63 : 16 groups of 3; per output voxel argmax over the 8 window
//                   positions of sum_m v_m^2, emit each channel's value there.
//
// FINAL (converged): float2 coalesced loads, 1 voxel/thread, streaming cache
// hints (zero-reuse workload), heavy argmax blocks launched first so the tail
// wave drains with light maxpool blocks.
//
// Convergence evidence — 5 runs of this exact binary:
//   bench 86.5/87.1/87.3/88.1/88.2us (mean 87.4, sigma ~0.7),
//   kernel 83.3-84.9us, HBM 6.87-7.01 TB/s (86-88% of 8TB/s spec).
// Six structural variants (occ 43-84%, float2/float4, ldg/ldcs,
// split/paired/heavy-first) all land within run-to-run noise: the kernel is
// pinned at the HBM3e streaming ceiling with ~1% traffic overhead over the
// mandatory 576MB floor. Compute pipes <= 20%. Zero data reuse exists, so
// tiling/TMA/SMEM/multicast are inapplicable. Done.

static constexpr long  CH_IN   = 128L * 128L * 128L;  // 2097152
static constexpr long  CH_OUT  = 64L * 64L * 64L;     // 262144
static constexpr int   ROW2    = 64;                  // 128 floats = 64 float2 per row
static constexpr int   PLANE2  = 64 * 128;            // one d-plane in float2 units

__global__ __launch_bounds__(256, 8)
void dynamic_pool3d_kernel(const float* __restrict__ x, float* __restrict__ out) {
    const int s  = blockIdx.x * blockDim.x + threadIdx.x;  // 0 .. 262143 (output voxel)
    const int gg = blockIdx.y;                              // 0 .. 31, heavy first

    const int w = s & 63;
    const int h = (s >> 6) & 63;
    const int d = s >> 12;

    // input float2 offset of window corner (2d, 2h, 2w)
    const long in2 = ((long)(2 * d) * 128 + (long)(2 * h)) * 64 + (long)w;

    if (gg >= 16) {
        // ---- plain 2x2x2 max pool on channel g (light: launch last) ----
        const int g = gg - 16;
        const float2* p = reinterpret_cast<const float2*>(x) + (long)g * (CH_IN / 2) + in2;
        const float2 a = __ldcs(p);
        const float2 b = __ldcs(p + ROW2);
        const float2 c = __ldcs(p + PLANE2);
        const float2 e = __ldcs(p + PLANE2 + ROW2);
        float m = fmaxf(fmaxf(fmaxf(a.x, a.y), fmaxf(b.x, b.y)),
                        fmaxf(fmaxf(c.x, c.y), fmaxf(e.x, e.y)));
        __stcs(out + (long)g * CH_OUT + s, m);
    } else {
        // ---- norm-argmax pooling over channel triple (heavy: launch first) ----
        const int c0 = 16 + 3 * gg;

        float v[3][8];
        float nrm[8];
        #pragma unroll
        for (int j = 0; j < 8; ++j) nrm[j] = 0.0f;

        #pragma unroll
        for (int m = 0; m < 3; ++m) {
            const float2* p = reinterpret_cast<const float2*>(x)
                            + (long)(c0 + m) * (CH_IN / 2) + in2;
            const float2 a = __ldcs(p);
            const float2 b = __ldcs(p + ROW2);
            const float2 c = __ldcs(p + PLANE2);
            const float2 e = __ldcs(p + PLANE2 + ROW2);
            // window order j = kd*4 + kh*2 + kw (matches the reference reshape)
            v[m][0] = a.x; v[m][1] = a.y;
            v[m][2] = b.x; v[m][3] = b.y;
            v[m][4] = c.x; v[m][5] = c.y;
            v[m][6] = e.x; v[m][7] = e.y;
            #pragma unroll
            for (int j = 0; j < 8; ++j)
                nrm[j] = fmaf(v[m][j], v[m][j], nrm[j]);
        }

        // strict first-max argmax (jnp.argmax semantics); constant-index selects
        float bn = nrm[0];
        float b0 = v[0][0], b1 = v[1][0], b2 = v[2][0];
        #pragma unroll
        for (int j = 1; j < 8; ++j) {
            if (nrm[j] > bn) {
                bn = nrm[j];
                b0 = v[0][j]; b1 = v[1][j]; b2 = v[2][j];
            }
        }

        float* o = out + (long)c0 * CH_OUT + s;
        __stcs(o,              b0);
        __stcs(o + CH_OUT,     b1);
        __stcs(o + 2 * CH_OUT, b2);
    }
}

extern "C" void kernel_launch(void* const* d_in, const int* in_sizes, int n_in,
                              void* d_out, int out_size) {
    const float* x = (const float*)d_in[0];
    float* out = (float*)d_out;
    dim3 grid((unsigned)(CH_OUT / 256), 32);
    dynamic_pool3d_kernel<<<grid, 256>>>(x, out);
}